// round 1
// baseline (speedup 1.0000x reference)
#include <cuda_runtime.h>
#include <cstdint>

#define NQ   14
#define DIM  (1 << NQ)     // 16384
#define TPB  512

// Storage swizzle: conflict-free for every access pattern used below.
__device__ __forceinline__ int phys_(int j) { return j ^ ((j >> 4) & 15); }

// Forward CNOT-chain index map: bit k of result = parity of bits k..13 of x.
__device__ __forceinline__ int pf_(int x) {
    x ^= x >> 1; x ^= x >> 2; x ^= x >> 4; x ^= x >> 8;
    return x;
}

// Fused RY(a) then RZ(theta) on a pair (u0 = |0> comp, u1 = |1> comp).
// RZ reduced to diag(1, e^{i theta}) (global phase dropped; probs only).
__device__ __forceinline__ void gate_pair(float2& u0, float2& u1,
                                          float ca, float sa, float pr, float pi) {
    float t0r = ca * u0.x - sa * u1.x;
    float t0i = ca * u0.y - sa * u1.y;
    float t1r = sa * u0.x + ca * u1.x;
    float t1i = sa * u0.y + ca * u1.y;
    u0.x = t0r; u0.y = t0i;
    u1.x = t1r * pr - t1i * pi;
    u1.y = t1i * pr + t1r * pi;
}

__global__ void __launch_bounds__(TPB, 1)
qsim_kernel(const float* __restrict__ sb,   // [B,14] state_batch
            const float* __restrict__ vp,   // [3,14,3] var_params
            const float* __restrict__ hw,   // [1,14] head_w
            const float* __restrict__ hb,   // [1] head_b
            float* __restrict__ out)        // [B]
{
    extern __shared__ unsigned char smraw[];
    float2* psi   = (float2*)smraw;                     // 131072 B
    float*  cx    = (float*)(smraw + 131072);           // 16 floats
    float*  sx    = cx + 16;                            // 16 floats
    float4* gates = (float4*)(sx + 16);                 // 42 float4 (aligned: 131200%16==0)
    float*  Wlo   = (float*)(gates + 42);               // 128
    float*  Whi   = Wlo + 128;                          // 128
    float*  red   = Whi + 128;                          // 16

    const int t = threadIdx.x;
    const int b = blockIdx.x;

    // ---- tiny parameter staging ----
    if (t < NQ) {
        float s, c;
        sincosf(0.5f * sb[b * NQ + t], &s, &c);
        cx[t] = c; sx[t] = s;
    }
    if (t >= 64 && t < 64 + 3 * NQ) {
        int lw = t - 64;                         // L*14 + w
        float a  = vp[lw * 3 + 0];
        float th = vp[lw * 3 + 1];
        float sa, ca, sp, cp;
        sincosf(0.5f * a, &sa, &ca);
        sincosf(th, &sp, &cp);                   // full theta (global phase dropped)
        gates[lw] = make_float4(ca, sa, cp, sp);
    }
    if (t >= 128 && t < 256) {                   // W for bits 0..6 (wires 13..7)
        int v = t - 128; float acc = 0.f;
        #pragma unroll
        for (int k = 0; k < 7; k++)
            acc += hw[13 - k] * (1.f - 2.f * (float)((v >> k) & 1));
        Wlo[v] = acc;
    }
    if (t >= 256 && t < 384) {                   // W for bits 7..13 (wires 6..0)
        int v = t - 256; float acc = 0.f;
        #pragma unroll
        for (int k = 0; k < 7; k++)
            acc += hw[6 - k] * (1.f - 2.f * (float)((v >> k) & 1));
        Whi[v] = acc;
    }
    __syncthreads();

    float2 v[32];

    // Group-gate appliers (all indices compile-time after unroll).
    auto applyA = [&](int L) {                   // wires 0..4 on bits 13..9 (local bit lb -> wire 4-lb)
        #pragma unroll
        for (int lb = 0; lb < 5; lb++) {
            float4 g = gates[L * 14 + (4 - lb)];
            #pragma unroll
            for (int m = 0; m < 16; m++) {
                int l0 = ((m >> lb) << (lb + 1)) | (m & ((1 << lb) - 1));
                int l1 = l0 | (1 << lb);
                gate_pair(v[l0], v[l1], g.x, g.y, g.z, g.w);
            }
        }
    };
    auto applyB = [&](int L) {                   // wires 5..9 on bits 8..4 (lb -> wire 9-lb)
        #pragma unroll
        for (int lb = 0; lb < 5; lb++) {
            float4 g = gates[L * 14 + (9 - lb)];
            #pragma unroll
            for (int m = 0; m < 16; m++) {
                int l0 = ((m >> lb) << (lb + 1)) | (m & ((1 << lb) - 1));
                int l1 = l0 | (1 << lb);
                gate_pair(v[l0], v[l1], g.x, g.y, g.z, g.w);
            }
        }
    };
    auto applyC16 = [&](int L) {                 // wires 10..13 on bits 3..0 (lb -> wire 13-lb), first 16 of v
        #pragma unroll
        for (int lb = 0; lb < 4; lb++) {
            float4 g = gates[L * 14 + (13 - lb)];
            #pragma unroll
            for (int m = 0; m < 8; m++) {
                int l0 = ((m >> lb) << (lb + 1)) | (m & ((1 << lb) - 1));
                int l1 = l0 | (1 << lb);
                gate_pair(v[l0], v[l1], g.x, g.y, g.z, g.w);
            }
        }
    };

    // ---- Pass 0: RX product-state init (closed form) + layer0 wires 0-4 ----
    {
        float mt = 1.f;
        #pragma unroll
        for (int k = 0; k < 9; k++)
            mt *= ((t >> k) & 1) ? sx[13 - k] : cx[13 - k];
        int pt = __popc(t);
        #pragma unroll
        for (int l = 0; l < 32; l++) {
            float m = mt;
            #pragma unroll
            for (int lb = 0; lb < 5; lb++)
                m *= ((l >> lb) & 1) ? sx[4 - lb] : cx[4 - lb];
            int k = (pt + __popc(l)) & 3;        // (-i)^k
            float2 a;
            a.x = (k == 0) ? m : ((k == 2) ? -m : 0.f);
            a.y = (k == 1) ? -m : ((k == 3) ? m : 0.f);
            v[l] = a;
        }
        applyA(0);
        #pragma unroll
        for (int l = 0; l < 32; l++)
            psi[phys_((l << 9) | t)] = v[l];
    }
    __syncthreads();

    #pragma unroll 1
    for (int L = 0; L < 3; L++) {
        // ---- Pass B: wires 5..9 ----
        {
            const int hi = (t >> 4) << 9;
            const int lo = t & 15;
            #pragma unroll
            for (int l = 0; l < 32; l++)
                v[l] = psi[phys_(hi | (l << 4) | lo)];
            applyB(L);
            #pragma unroll
            for (int l = 0; l < 32; l++)
                psi[phys_(hi | (l << 4) | lo)] = v[l];
        }
        __syncthreads();

        // ---- Pass C: wires 10..13 (two 16-element chunks per thread) ----
        #pragma unroll
        for (int h = 0; h < 2; h++) {
            const int tt = t + h * TPB;
            #pragma unroll
            for (int l = 0; l < 16; l++)
                v[l] = psi[phys_((tt << 4) | l)];
            applyC16(L);
            #pragma unroll
            for (int l = 0; l < 16; l++)
                psi[phys_((tt << 4) | l)] = v[l];
        }
        __syncthreads();

        if (L < 2) {
            // ---- Pass A' of next layer: CNOT-chain fold (read at inverse-permuted
            // index) + next layer's wires 0..4. Read-all / sync / write-all.
            #pragma unroll
            for (int l = 0; l < 32; l++) {
                int j = (l << 9) | t;
                v[l] = psi[phys_(j ^ (j >> 1))];     // F^{-1}(j)
            }
            applyA(L + 1);
            __syncthreads();
            #pragma unroll
            for (int l = 0; l < 32; l++)
                psi[phys_((l << 9) | t)] = v[l];
            __syncthreads();
        }
    }

    // ---- Measurement: final chain folded into weight lookup ----
    // out[b] = sum_i |s[i]|^2 * W(F(i)) + hb
    float acc = 0.f;
    #pragma unroll
    for (int k = 0; k < 32; k++) {
        int i = t + (k << 9);
        float2 a = psi[phys_(i)];
        int f = pf_(i);
        acc += (a.x * a.x + a.y * a.y) * (Wlo[f & 127] + Whi[f >> 7]);
    }
    #pragma unroll
    for (int o = 16; o > 0; o >>= 1)
        acc += __shfl_xor_sync(0xffffffffu, acc, o);
    if ((t & 31) == 0) red[t >> 5] = acc;
    __syncthreads();
    if (t == 0) {
        float s = 0.f;
        #pragma unroll
        for (int w = 0; w < TPB / 32; w++) s += red[w];
        out[b] = s + hb[0];
    }
}

extern "C" void kernel_launch(void* const* d_in, const int* in_sizes, int n_in,
                              void* d_out, int out_size) {
    const float* sb = (const float*)d_in[0];   // state_batch [B,14]
    const float* vp = (const float*)d_in[1];   // var_params [3,14,3]
    const float* hw = (const float*)d_in[2];   // head_w [1,14]
    const float* hb = (const float*)d_in[3];   // head_b [1]
    float* out = (float*)d_out;

    const int B = in_sizes[0] / NQ;
    const size_t smem = 131072            // psi
                      + 64 + 64           // cx, sx
                      + 42 * 16           // gates
                      + 512 + 512         // Wlo, Whi
                      + 64;               // red
    cudaFuncSetAttribute(qsim_kernel,
                         cudaFuncAttributeMaxDynamicSharedMemorySize, (int)smem);
    qsim_kernel<<<B, TPB, smem>>>(sb, vp, hw, hb, out);
}